// round 15
// baseline (speedup 1.0000x reference)
#include <cuda_runtime.h>

#define LAYERS   8
#define WIDTH    128
#define DDIM     64
#define PPD      23          // 3*KNOTS-1
#define BATCH    16384
#define TB       64          // batch rows per CTA
#define NTHREADS 256
#define DGC      8           // dims per chunk (1 per warp)
#define NCHUNK   (DDIM/DGC)  // 8
#define XPAD     68
#define HPAD     132
#define WQPAD    20          // 16-col sub-block staging row stride
#define WROWS    192         // 8 dims x 24 (param rows, padded)
#define WBUF     (WROWS*WQPAD)   // 3840
#define BI       4.0f

// shared memory layout (float offsets)
#define OFF_X0   0
#define OFF_X1   (TB*XPAD)                    // 4352
#define OFF_H    (2*TB*XPAD)                  // 8704
#define OFF_WS   (2*TB*XPAD + TB*HPAD)        // 17152
#define SMEM_FLOATS (OFF_WS + 2*WBUF)         // 24832
#define SMEM_BYTES  (SMEM_FLOATS*4)           // 99328 B -> 2 CTAs/SM

// Pre-masked, degree-sorted weights (static device scratch).
// g_Wom padded +128: staging of the padded 24th param row of the last dim
// reads one row past the logical end.
__device__ float g_W1m[2*LAYERS*WIDTH*DDIM];
__device__ float g_Wom[2*LAYERS*DDIM*PPD*WIDTH + 128];
__device__ float g_b1p[2*LAYERS*WIDTH];

// ---------------------------------------------------------------------------
__device__ __forceinline__ unsigned long long ffma2(unsigned long long a,
                                                    unsigned long long b,
                                                    unsigned long long c)
{
    unsigned long long d;
    asm("fma.rn.f32x2 %0, %1, %2, %3;" : "=l"(d) : "l"(a), "l"(b), "l"(c));
    return d;
}
__device__ __forceinline__ float2 unpack2(unsigned long long v)
{
    float2 r;
    asm("mov.b64 {%0, %1}, %2;" : "=f"(r.x), "=f"(r.y) : "l"(v));
    return r;
}

// softplus = max(v,0) + log(1 + exp(-|v|))
__device__ __forceinline__ float softplus_fast(float v)
{
    float t = __expf(-fabsf(v));
    return fmaxf(v, 0.f) + __logf(1.f + t);
}

// ---------------------------------------------------------------------------
// Degree-sorted hidden permutation.
// ---------------------------------------------------------------------------
__host__ __device__ __forceinline__ int sdeg(int j) { return (j < 6) ? (j/3) : ((j-2)>>1); }
__host__ __device__ __forceinline__ int permf(int j)
{
    if (j < 3)  return (j == 0) ? 0 : (j == 1 ? 63 : 126);
    if (j < 6)  return (j == 3) ? 1 : (j == 4 ? 64 : 127);
    int v = (j - 2) >> 1;
    return ((j & 1) == 0) ? v : v + 63;
}
__device__ __forceinline__ int kmax_of(int d)
{
    int n = (d == 0) ? 0 : (d == 1 ? 3 : 2*d + 2);
    n = (n + 7) & ~7;
    return n > 128 ? 128 : n;
}

// ---------------------------------------------------------------------------
// Prep: mask + permute weights once per launch.
// ---------------------------------------------------------------------------
__global__ void prep_kernel(const float* __restrict__ fW1, const float* __restrict__ fWo,
                            const float* __restrict__ gW1, const float* __restrict__ gWo,
                            const float* __restrict__ fb1, const float* __restrict__ gb1)
{
    const int N1 = LAYERS*WIDTH*DDIM;
    const int N2 = LAYERS*DDIM*PPD*WIDTH;
    const int stride = gridDim.x * blockDim.x;
    const int t0 = blockIdx.x*blockDim.x + threadIdx.x;

    for (int i = t0; i < 2*N1; i += stride) {
        int fl = i / N1, j = i - fl*N1;
        int row = (j >> 6) & (WIDTH-1);
        int c = j & (DDIM-1);
        int l = j >> 13;
        const float* s = fl ? gW1 : fW1;
        int src = permf(row);
        g_W1m[i] = (c <= sdeg(row)) ? s[l*WIDTH*DDIM + src*DDIM + c] : 0.f;
    }
    for (int i = t0; i < 2*N2; i += stride) {
        int fl = i / N2, j = i - fl*N2;
        int col = j & (WIDTH-1);
        int o = (j >> 7) % (DDIM*PPD);
        int l = j / (DDIM*PPD*WIDTH);
        int d = o / PPD;
        const float* s = fl ? gWo : fWo;
        int src = permf(col);
        g_Wom[i] = (sdeg(col) < d) ? s[l*(DDIM*PPD)*WIDTH + o*WIDTH + src] : 0.f;
    }
    if (t0 < 128) g_Wom[2*N2 + t0] = 0.f;
    for (int i = t0; i < 2*LAYERS*WIDTH; i += stride) {
        int fl = i / (LAYERS*WIDTH), j = i - fl*(LAYERS*WIDTH);
        int l = j >> 7, w = j & (WIDTH-1);
        const float* s = fl ? gb1 : fb1;
        g_b1p[i] = s[l*WIDTH + permf(w)];
    }
}

// ---------------------------------------------------------------------------
// Wout sub-block stage: 8 dims x 24 param-rows x 16 cols -> buf.
// rr -> (dd, pp) via mul-shift /24; padded pp=23 row reads are covered by
// the +128 pad on g_Wom.  Predicated per dim on kmax.
// ---------------------------------------------------------------------------
__device__ __forceinline__ void stage_wout(
    float* buf, const float* __restrict__ Wol, int d0, int s, int tid)
{
#pragma unroll
    for (int it = 0; it < 3; it++) {
        int i = tid + it*NTHREADS;          // 768 float4s
        int rr = i >> 2, c4 = i & 3;        // rr: 0..191
        int dd = (rr * 2731) >> 16;         // rr / 24
        int pp = rr - dd*24;
        if (kmax_of(d0 + dd) > 16*s) {
            float4 v = *(const float4*)&Wol[((d0+dd)*PPD + pp)*WIDTH + s*16 + c4*4];
            *(float4*)&buf[rr*WQPAD + c4*4] = v;
        }
    }
}

// W1 sub-block stage: 128 hidden rows x 16 cols; octet o active if o >= 4s.
__device__ __forceinline__ void stage_w1(
    float* buf, const float* __restrict__ W1l, int s, int tid)
{
#pragma unroll
    for (int it = 0; it < 2; it++) {
        int i = tid + it*NTHREADS;          // 512 float4s
        int rr = i >> 2, c4 = i & 3;
        if ((rr >> 3) >= 4*s) {
            float4 v = *(const float4*)&W1l[rr*DDIM + s*16 + c4*4];
            *(float4*)&buf[rr*WQPAD + c4*4] = v;
        }
    }
}

// ---------------------------------------------------------------------------
// Main kernel: one CTA (256 thr, 8 warps) = 64 rows through all 8 layers;
// 2 CTAs/SM @ 128 regs.  GEMM2: single merged pass (23 params), 1 dim/warp,
// lane owns rows {lane, lane+32}; 16-col ping-pong staging.  Spline fused.
// ---------------------------------------------------------------------------
__global__ __launch_bounds__(NTHREADS, 2)
void maf_kernel(const float* __restrict__ xin_f, const float* __restrict__ xin_g,
                const float* __restrict__ f_bout, const float* __restrict__ g_bout,
                float* __restrict__ out)
{
    extern __shared__ float sm[];
    const int tid   = threadIdx.x;
    const int flow  = blockIdx.y;
    const int row0  = blockIdx.x * TB;
    const int warpi = tid >> 5;    // 0..7
    const int lane  = tid & 31;

    const float* xin   = flow ? xin_g  : xin_f;
    const float* boutg = flow ? g_bout : f_bout;
    const float* b1p   = g_b1p + flow * (LAYERS*WIDTH);
    const float* W1m   = g_W1m + flow * (LAYERS*WIDTH*DDIM);
    const float* Wom   = g_Wom + flow * (LAYERS*DDIM*PPD*WIDTH);

    for (int i = tid; i < TB*DDIM; i += NTHREADS) {
        int r = i >> 6, d = i & 63;
        sm[OFF_X0 + r*XPAD + d] = xin[row0*DDIM + i];
    }

    const float C1 = 8.0f / 1.01f;
    const float CADJ = 0.00125f;

    float ldacc[2] = {0.f, 0.f};
    int cur = OFF_X0, nxt = OFF_X1;

    __syncthreads();

    for (int layer = 0; layer < LAYERS; layer++) {
        // ================= GEMM1: H = relu(X @ W1p^T + b1) =================
        // warp w owns hidden octets {w, 15-w}; lane owns rows {lane, lane+32}.
        {
            const float* W1l = W1m + layer*WIDTH*DDIM;
            const int oa = warpi, ob = 15 - warpi;

            unsigned long long acc[2][16];  // [row][0-7: octet a, 8-15: octet b]
#pragma unroll
            for (int ri = 0; ri < 2; ri++)
#pragma unroll
                for (int p = 0; p < 16; p++) acc[ri][p] = 0ull;

            stage_w1(&sm[OFF_WS], W1l, 0, tid);
            __syncthreads();

            for (int s = 0; s < 4; s++) {
                const float* buf = &sm[OFF_WS + (s & 1)*WBUF];
                int ba = 4*(oa+1) - 16*s;  ba = ba < 0 ? 0 : (ba > 16 ? 16 : ba);
                int bb = 4*(ob+1) - 16*s;  bb = bb < 0 ? 0 : (bb > 16 ? 16 : bb);
                const int ka4 = ba >> 2, kb4 = bb >> 2;   // ka4 <= kb4 (oa < ob)
                const float* xr0 = &sm[cur + (lane     )*XPAD + s*16];
                const float* xr1 = &sm[cur + (lane + 32)*XPAD + s*16];
#pragma unroll 2
                for (int kk = 0; kk < kb4; kk++) {
                    ulonglong2 x0 = *(const ulonglong2*)&xr0[kk*4];
                    ulonglong2 x1 = *(const ulonglong2*)&xr1[kk*4];
                    if (kk < ka4) {
#pragma unroll
                        for (int p = 0; p < 8; p++) {
                            ulonglong2 wv = *(const ulonglong2*)&buf[(8*oa+p)*WQPAD + kk*4];
                            acc[0][p] = ffma2(x0.x, wv.x, acc[0][p]);
                            acc[0][p] = ffma2(x0.y, wv.y, acc[0][p]);
                            acc[1][p] = ffma2(x1.x, wv.x, acc[1][p]);
                            acc[1][p] = ffma2(x1.y, wv.y, acc[1][p]);
                        }
                    }
#pragma unroll
                    for (int p = 0; p < 8; p++) {
                        ulonglong2 wv = *(const ulonglong2*)&buf[(8*ob+p)*WQPAD + kk*4];
                        acc[0][8+p] = ffma2(x0.x, wv.x, acc[0][8+p]);
                        acc[0][8+p] = ffma2(x0.y, wv.y, acc[0][8+p]);
                        acc[1][8+p] = ffma2(x1.x, wv.x, acc[1][8+p]);
                        acc[1][8+p] = ffma2(x1.y, wv.y, acc[1][8+p]);
                    }
                }
                if (s + 1 < 4)
                    stage_w1(&sm[OFF_WS + ((s+1) & 1)*WBUF], W1l, s + 1, tid);
                __syncthreads();
            }

            float4 ba4 = *(const float4*)&b1p[layer*WIDTH + 8*oa];
            float4 ba5 = *(const float4*)&b1p[layer*WIDTH + 8*oa + 4];
            float4 bb4 = *(const float4*)&b1p[layer*WIDTH + 8*ob];
            float4 bb5 = *(const float4*)&b1p[layer*WIDTH + 8*ob + 4];
            float bav[8] = {ba4.x,ba4.y,ba4.z,ba4.w, ba5.x,ba5.y,ba5.z,ba5.w};
            float bbv[8] = {bb4.x,bb4.y,bb4.z,bb4.w, bb5.x,bb5.y,bb5.z,bb5.w};
#pragma unroll
            for (int ri = 0; ri < 2; ri++) {
                int r = lane + 32*ri;
                float ha[8], hb[8];
#pragma unroll
                for (int p = 0; p < 8; p++) {
                    float2 ua = unpack2(acc[ri][p]);
                    ha[p] = fmaxf(ua.x + ua.y + bav[p], 0.f);
                    float2 ub = unpack2(acc[ri][8+p]);
                    hb[p] = fmaxf(ub.x + ub.y + bbv[p], 0.f);
                }
                *(float4*)&sm[OFF_H + r*HPAD + 8*oa]     = make_float4(ha[0],ha[1],ha[2],ha[3]);
                *(float4*)&sm[OFF_H + r*HPAD + 8*oa + 4] = make_float4(ha[4],ha[5],ha[6],ha[7]);
                *(float4*)&sm[OFF_H + r*HPAD + 8*ob]     = make_float4(hb[0],hb[1],hb[2],hb[3]);
                *(float4*)&sm[OFF_H + r*HPAD + 8*ob + 4] = make_float4(hb[4],hb[5],hb[6],hb[7]);
            }
        }
        __syncthreads();   // H ready

        // ========== GEMM2 (merged 23-param pass) + fused spline ==========
        for (int chunk = 0; chunk < NCHUNK; chunk++) {
            const int d0 = chunk * DGC;
            const int d  = d0 + warpi;
            const int kmax = kmax_of(d);                     // warp-uniform
            const int ns   = (kmax_of(d0 + 7) + 15) >> 4;    // CTA-uniform
            const float* Wol = Wom + layer*DDIM*PPD*WIDTH;
            const float* bo  = boutg + (layer*DDIM + d)*PPD;

            unsigned long long acc[2][PPD];
#pragma unroll
            for (int ri = 0; ri < 2; ri++)
#pragma unroll
                for (int p = 0; p < PPD; p++) acc[ri][p] = 0ull;

            stage_wout(&sm[OFF_WS], Wol, d0, 0, tid);
            __syncthreads();

            for (int s = 0; s < ns; s++) {
                int bound = kmax - 16*s;
                bound = bound < 0 ? 0 : (bound > 16 ? 16 : bound);
                const float* hbase = &sm[OFF_H + s*16];
                const float* wsp   = &sm[OFF_WS + (s & 1)*WBUF + (warpi*24)*WQPAD];
#pragma unroll 2
                for (int kk = 0; kk < (bound >> 2); kk++) {
                    ulonglong2 h0 = *(const ulonglong2*)&hbase[(lane     )*HPAD + kk*4];
                    ulonglong2 h1 = *(const ulonglong2*)&hbase[(lane + 32)*HPAD + kk*4];
#pragma unroll
                    for (int p = 0; p < PPD; p++) {
                        ulonglong2 wv = *(const ulonglong2*)&wsp[p*WQPAD + kk*4];
                        acc[0][p] = ffma2(h0.x, wv.x, acc[0][p]);
                        acc[0][p] = ffma2(h0.y, wv.y, acc[0][p]);
                        acc[1][p] = ffma2(h1.x, wv.x, acc[1][p]);
                        acc[1][p] = ffma2(h1.y, wv.y, acc[1][p]);
                    }
                }
                if (s + 1 < ns)
                    stage_wout(&sm[OFF_WS + ((s+1) & 1)*WBUF], Wol, d0, s + 1, tid);
                __syncthreads();
            }

            // ---- fused spline epilogue, one row at a time ----
#pragma unroll
            for (int ri = 0; ri < 2; ri++) {
                float par[PPD];
#pragma unroll
                for (int p = 0; p < PPD; p++) {
                    float2 u = unpack2(acc[ri][p]);
                    par[p] = u.x + u.y + bo[p];
                }

                // widths
                float mw = par[0];
#pragma unroll
                for (int j = 1; j < 8; j++) mw = fmaxf(mw, par[j]);
                float ew[8]; float swv = 0.f;
#pragma unroll
                for (int j = 0; j < 8; j++) { ew[j] = __expf(par[j] - mw); swv += ew[j]; }
                float iscw = __frcp_rn(swv) * C1;
                float cadj = CADJ * C1;

                float xraw = sm[cur + (lane + 32*ri)*XPAD + d];
                float xc = fminf(fmaxf(xraw, -BI), BI);

                float xl = -BI;
                float xk = -BI, xk1 = -BI;
                int k = 0;
#pragma unroll
                for (int j = 0; j < 8; j++) {
                    float wj = ew[j]*iscw + cadj;
                    float xr2 = xl + wj;
                    if (xc >= xl) { k = j; xk = xl; xk1 = xr2; }
                    xl = xr2;
                }
                float invdx = __frcp_rn(xk1 - xk);
                float xi = (xc - xk) * invdx;

                // heights
                float mh = par[8];
#pragma unroll
                for (int j = 1; j < 8; j++) mh = fmaxf(mh, par[8+j]);
                float eh[8]; float shv = 0.f;
#pragma unroll
                for (int j = 0; j < 8; j++) { eh[j] = __expf(par[8+j] - mh); shv += eh[j]; }
                float isch = __frcp_rn(shv) * C1;

                float yl = -BI;
                float yk = -BI, yk1 = -BI;
#pragma unroll
                for (int j = 0; j < 8; j++) {
                    float hj = eh[j]*isch + cadj;
                    float yr2 = yl + hj;
                    if (j == k) { yk = yl; yk1 = yr2; }
                    yl = yr2;
                }
                float dyv = yk1 - yk;
                float sk  = dyv * invdx;

                // derivatives (2 selected only)
                float vkm1 = 0.f, vk = 0.f;
#pragma unroll
                for (int j = 0; j < 7; j++) {
                    float v = par[16+j];
                    if (j == k - 1) vkm1 = v;
                    if (j == k)     vk   = v;
                }
                float dk  = (k >= 1) ? (softplus_fast(vkm1) + 0.001f) : 1.f;
                float dk1 = (k <= 6) ? (softplus_fast(vk)   + 0.001f) : 1.f;

                float omx = 1.f - xi;
                float xiomx = xi * omx;
                float den = sk + (dk1 + dk - 2.f*sk) * xiomx;
                float invden = __frcp_rn(den);
                float nume = sk*xi*xi + dk*xiomx;
                float outv = yk + dyv * nume * invden;
                float ldn = dk1*xi*xi + 2.f*sk*xiomx + dk*omx*omx;
                float ld = __logf(sk*sk*ldn*(invden*invden));

                bool inside = (xraw > -BI) && (xraw < BI);
                float xo2 = inside ? outv : xraw;
                sm[nxt + (lane + 32*ri)*XPAD + (DDIM-1 - d)] = xo2;  // reversal fused
                ldacc[ri] += inside ? ld : 0.f;
            }
        }

        __syncthreads();   // X(nxt) ready
        int t = cur; cur = nxt; nxt = t;
    }

    // ---- outputs: [xo (B*64) | ldf (B) | yo (B*64) | ldg (B)]
    const int xbase  = flow ? (BATCH*DDIM + BATCH) : 0;
    const int ldbase = flow ? (2*BATCH*DDIM + BATCH) : (BATCH*DDIM);

    for (int i = tid; i < TB*DDIM; i += NTHREADS) {
        int rr = i >> 6, dd = i & 63;
        out[xbase + row0*DDIM + i] = sm[cur + rr*XPAD + dd];
    }

    // log-det reduction: 8 dim-class partials per row (class = warpi)
    float* red = &sm[OFF_WS];
#pragma unroll
    for (int ri = 0; ri < 2; ri++)
        red[(lane + 32*ri)*8 + warpi] = ldacc[ri];
    __syncthreads();
    if (tid < TB) {
        float s = 0.f;
#pragma unroll
        for (int j = 0; j < 8; j++) s += red[tid*8 + j];
        out[ldbase + row0 + tid] = s;
    }
}

// ---------------------------------------------------------------------------
extern "C" void kernel_launch(void* const* d_in, const int* in_sizes, int n_in,
                              void* d_out, int out_size)
{
    const float* x      = (const float*)d_in[0];
    const float* y      = (const float*)d_in[1];
    const float* f_W1   = (const float*)d_in[2];
    const float* f_b1   = (const float*)d_in[3];
    const float* f_Wout = (const float*)d_in[4];
    const float* f_bout = (const float*)d_in[5];
    const float* g_W1   = (const float*)d_in[6];
    const float* g_b1   = (const float*)d_in[7];
    const float* g_Wout = (const float*)d_in[8];
    const float* g_bout = (const float*)d_in[9];
    float* out = (float*)d_out;

    cudaFuncSetAttribute(maf_kernel, cudaFuncAttributeMaxDynamicSharedMemorySize, SMEM_BYTES);

    prep_kernel<<<1024, 256>>>(f_W1, f_Wout, g_W1, g_Wout, f_b1, g_b1);

    dim3 grid(BATCH/TB, 2);
    maf_kernel<<<grid, NTHREADS, SMEM_BYTES>>>(x, y, f_bout, g_bout, out);
}

// round 16
// speedup vs baseline: 1.3957x; 1.3957x over previous
#include <cuda_runtime.h>

#define LAYERS   8
#define WIDTH    128
#define DDIM     64
#define KNOTS    8
#define PPD      23          // 3*KNOTS-1
#define BATCH    16384
#define TB       64          // batch rows per CTA
#define NTHREADS 512
#define DG       16          // dims per chunk (1 per warp)
#define NCHUNK   (DDIM/DG)   // 4
#define XPAD     68
#define HPAD     132
#define WQPAD    36          // 32-col quarter staging row stride
#define BUFSZ    (128*WQPAD) // one ping-pong buffer (128 rows)
#define BI       4.0f

// shared memory layout (float offsets)
#define OFF_X0   0
#define OFF_X1   (TB*XPAD)                    // 4352
#define OFF_H    (2*TB*XPAD)                  // 8704
#define OFF_WS   (2*TB*XPAD + TB*HPAD)        // 17152
#define SMEM_FLOATS (OFF_WS + 2*BUFSZ)        // 17152 + 9216 = 26368
#define SMEM_BYTES  (SMEM_FLOATS*4)           // 105472 B -> 2 CTAs/SM

// Pre-masked, degree-sorted weights (static device scratch).
// g_Wom padded +128: pass-3 staging reads one row past the logical end.
__device__ float g_W1m[2*LAYERS*WIDTH*DDIM];
__device__ float g_Wom[2*LAYERS*DDIM*PPD*WIDTH + 128];
__device__ float g_b1p[2*LAYERS*WIDTH];

// ---------------------------------------------------------------------------
// packed fp32x2 FMA: 2 MACs per fma-pipe issue slot
// ---------------------------------------------------------------------------
__device__ __forceinline__ unsigned long long ffma2(unsigned long long a,
                                                    unsigned long long b,
                                                    unsigned long long c)
{
    unsigned long long d;
    asm("fma.rn.f32x2 %0, %1, %2, %3;" : "=l"(d) : "l"(a), "l"(b), "l"(c));
    return d;
}
__device__ __forceinline__ float2 unpack2(unsigned long long v)
{
    float2 r;
    asm("mov.b64 {%0, %1}, %2;" : "=f"(r.x), "=f"(r.y) : "l"(v));
    return r;
}

// softplus = max(v,0) + log(1 + exp(-|v|))   (2 MUFU, no library tail)
__device__ __forceinline__ float softplus_fast(float v)
{
    float t = __expf(-fabsf(v));
    return fmaxf(v, 0.f) + __logf(1.f + t);
}

// ---------------------------------------------------------------------------
// Degree-sorted hidden permutation.
// ---------------------------------------------------------------------------
__host__ __device__ __forceinline__ int sdeg(int j) { return (j < 6) ? (j/3) : ((j-2)>>1); }
__host__ __device__ __forceinline__ int permf(int j)
{
    if (j < 3)  return (j == 0) ? 0 : (j == 1 ? 63 : 126);
    if (j < 6)  return (j == 3) ? 1 : (j == 4 ? 64 : 127);
    int v = (j - 2) >> 1;
    return ((j & 1) == 0) ? v : v + 63;
}
// prefix length of dim d over sorted hidden, rounded up to 8
__device__ __forceinline__ int kmax_of(int d)
{
    int n = (d == 0) ? 0 : (d == 1 ? 3 : 2*d + 2);
    n = (n + 7) & ~7;
    return n > 128 ? 128 : n;
}

// ---------------------------------------------------------------------------
// Prep: mask + permute weights once per launch.
// ---------------------------------------------------------------------------
__global__ void prep_kernel(const float* __restrict__ fW1, const float* __restrict__ fWo,
                            const float* __restrict__ gW1, const float* __restrict__ gWo,
                            const float* __restrict__ fb1, const float* __restrict__ gb1)
{
    const int N1 = LAYERS*WIDTH*DDIM;
    const int N2 = LAYERS*DDIM*PPD*WIDTH;
    const int stride = gridDim.x * blockDim.x;
    const int t0 = blockIdx.x*blockDim.x + threadIdx.x;

    for (int i = t0; i < 2*N1; i += stride) {
        int fl = i / N1, j = i - fl*N1;
        int row = (j >> 6) & (WIDTH-1);
        int c = j & (DDIM-1);
        int l = j >> 13;
        const float* s = fl ? gW1 : fW1;
        int src = permf(row);
        g_W1m[i] = (c <= sdeg(row)) ? s[l*WIDTH*DDIM + src*DDIM + c] : 0.f;
    }
    for (int i = t0; i < 2*N2; i += stride) {
        int fl = i / N2, j = i - fl*N2;
        int col = j & (WIDTH-1);
        int o = (j >> 7) % (DDIM*PPD);
        int l = j / (DDIM*PPD*WIDTH);
        int d = o / PPD;
        const float* s = fl ? gWo : fWo;
        int src = permf(col);
        g_Wom[i] = (sdeg(col) < d) ? s[l*(DDIM*PPD)*WIDTH + o*WIDTH + src] : 0.f;
    }
    if (t0 < 128) g_Wom[2*N2 + t0] = 0.f;   // pad tail
    for (int i = t0; i < 2*LAYERS*WIDTH; i += stride) {
        int fl = i / (LAYERS*WIDTH), j = i - fl*(LAYERS*WIDTH);
        int l = j >> 7, w = j & (WIDTH-1);
        const float* s = fl ? gb1 : fb1;
        g_b1p[i] = s[l*WIDTH + permf(w)];
    }
}

// ---------------------------------------------------------------------------
// GEMM2 quarter stage: 16 dims x 8 params x 32 cols of Wout -> buffer (q&1).
// Predicated: dim dd is staged only if its compute bound reaches quarter q.
// ---------------------------------------------------------------------------
__device__ __forceinline__ void stage_q(
    float* sm, const float* __restrict__ Wol, int d0, int pbase, int q)
{
    float* buf = &sm[OFF_WS + (q & 1)*BUFSZ];
#pragma unroll
    for (int it = 0; it < 2; it++) {
        int i = threadIdx.x + it*NTHREADS;      // 1024 float4s
        int rr = i >> 3, c4 = i & 7;
        int dd = rr >> 3, pp = rr & 7;
        if (kmax_of(d0 + dd) > 32*q) {
            float4 v = *(const float4*)&Wol[((d0+dd)*PPD + pbase + pp)*WIDTH + q*32 + c4*4];
            *(float4*)&buf[rr*WQPAD + c4*4] = v;
        }
    }
}

// ---------------------------------------------------------------------------
// GEMM2 pass (phases 1/2): PCNT params x 2 rows over this warp's dim
// K-prefix.  Quarter-grain ping-pong staging.
// ---------------------------------------------------------------------------
template<int PBASE, int PCNT>
__device__ __forceinline__ void gemm2_pass(
    float* sm, const float* __restrict__ Wol, const float* __restrict__ bo,
    int d0, int dl, int lane, int nq, int kmax, float out[2][8])
{
    unsigned long long acc[2][PCNT];
#pragma unroll
    for (int ri = 0; ri < 2; ri++)
#pragma unroll
        for (int p = 0; p < PCNT; p++) acc[ri][p] = 0ull;

    stage_q(sm, Wol, d0, PBASE, 0);
    __syncthreads();

    for (int q = 0; q < nq; q++) {
        int bound = kmax - 32*q;                    // warp-uniform
        bound = bound < 0 ? 0 : (bound > 32 ? 32 : bound);
        const float* hbase = &sm[OFF_H + q*32];
        const float* wsp   = &sm[OFF_WS + (q & 1)*BUFSZ + (dl*8)*WQPAD];
#pragma unroll 4
        for (int k4 = 0; k4 < (bound >> 2); k4++) {
            ulonglong2 h0 = *(const ulonglong2*)&hbase[(lane     )*HPAD + k4*4];
            ulonglong2 h1 = *(const ulonglong2*)&hbase[(lane + 32)*HPAD + k4*4];
#pragma unroll
            for (int p = 0; p < PCNT; p++) {
                ulonglong2 wv = *(const ulonglong2*)&wsp[p*WQPAD + k4*4];
                acc[0][p] = ffma2(h0.x, wv.x, acc[0][p]);
                acc[0][p] = ffma2(h0.y, wv.y, acc[0][p]);
                acc[1][p] = ffma2(h1.x, wv.x, acc[1][p]);
                acc[1][p] = ffma2(h1.y, wv.y, acc[1][p]);
            }
        }
        if (q + 1 < nq) stage_q(sm, Wol, d0, PBASE, q + 1);
        __syncthreads();
    }

#pragma unroll
    for (int ri = 0; ri < 2; ri++)
#pragma unroll
        for (int p = 0; p < PCNT; p++) {
            float2 u = unpack2(acc[ri][p]);
            out[ri][p] = u.x + u.y + bo[PBASE + p];
        }
}

// ---------------------------------------------------------------------------
// GEMM2 phase 3 (selective): only the 2 derivative params actually used
// (rows k-1 and k, known from phase 1) are accumulated.  Lane-dependent W
// rows; bank-conflict-free (row stride 36 -> bank offset 4*k, distinct per
// distinct k; equal k merges as broadcast).  8 FFMA2 + 4 W loads per k4
// instead of 28 + 7.
// ---------------------------------------------------------------------------
__device__ __forceinline__ void gemm2_pass3(
    float* sm, const float* __restrict__ Wol,
    int d0, int dl, int lane, int nq, int kmax,
    const int st_k[2], float dotA[2], float dotB[2])
{
    unsigned long long accA[2] = {0ull, 0ull};
    unsigned long long accB[2] = {0ull, 0ull};
    const int rA0 = dl*8 + max(st_k[0] - 1, 0);
    const int rB0 = dl*8 + min(st_k[0], 6);
    const int rA1 = dl*8 + max(st_k[1] - 1, 0);
    const int rB1 = dl*8 + min(st_k[1], 6);

    stage_q(sm, Wol, d0, 16, 0);
    __syncthreads();

    for (int q = 0; q < nq; q++) {
        int bound = kmax - 32*q;                    // warp-uniform
        bound = bound < 0 ? 0 : (bound > 32 ? 32 : bound);
        const float* hbase = &sm[OFF_H + q*32];
        const float* bufq  = &sm[OFF_WS + (q & 1)*BUFSZ];
#pragma unroll 4
        for (int k4 = 0; k4 < (bound >> 2); k4++) {
            ulonglong2 h0 = *(const ulonglong2*)&hbase[(lane     )*HPAD + k4*4];
            ulonglong2 h1 = *(const ulonglong2*)&hbase[(lane + 32)*HPAD + k4*4];
            ulonglong2 wA0 = *(const ulonglong2*)&bufq[rA0*WQPAD + k4*4];
            ulonglong2 wB0 = *(const ulonglong2*)&bufq[rB0*WQPAD + k4*4];
            ulonglong2 wA1 = *(const ulonglong2*)&bufq[rA1*WQPAD + k4*4];
            ulonglong2 wB1 = *(const ulonglong2*)&bufq[rB1*WQPAD + k4*4];
            accA[0] = ffma2(h0.x, wA0.x, accA[0]);
            accA[0] = ffma2(h0.y, wA0.y, accA[0]);
            accB[0] = ffma2(h0.x, wB0.x, accB[0]);
            accB[0] = ffma2(h0.y, wB0.y, accB[0]);
            accA[1] = ffma2(h1.x, wA1.x, accA[1]);
            accA[1] = ffma2(h1.y, wA1.y, accA[1]);
            accB[1] = ffma2(h1.x, wB1.x, accB[1]);
            accB[1] = ffma2(h1.y, wB1.y, accB[1]);
        }
        if (q + 1 < nq) stage_q(sm, Wol, d0, 16, q + 1);
        __syncthreads();
    }

#pragma unroll
    for (int ri = 0; ri < 2; ri++) {
        float2 ua = unpack2(ri == 0 ? accA[0] : accA[1]);
        float2 ub = unpack2(ri == 0 ? accB[0] : accB[1]);
        dotA[ri] = ua.x + ua.y;
        dotB[ri] = ub.x + ub.y;
    }
}

// ---------------------------------------------------------------------------
// Main kernel: one CTA (512 thr) = 64 rows through all 8 layers; 2 CTAs/SM.
// Warp w owns dim d0+w (GEMM2) / hidden quads {w, 31-w} (GEMM1); lane owns
// rows {lane, lane+32}.  Spline streamed in 3 phases; MUFU-minimized.
// ---------------------------------------------------------------------------
__global__ __launch_bounds__(NTHREADS, 2)
void maf_kernel(const float* __restrict__ xin_f, const float* __restrict__ xin_g,
                const float* __restrict__ f_bout, const float* __restrict__ g_bout,
                float* __restrict__ out)
{
    extern __shared__ float sm[];
    const int tid   = threadIdx.x;
    const int flow  = blockIdx.y;
    const int row0  = blockIdx.x * TB;
    const int warpi = tid >> 5;    // 0..15
    const int lane  = tid & 31;
    const int dl    = warpi;       // dim lane within chunk

    const float* xin   = flow ? xin_g  : xin_f;
    const float* boutg = flow ? g_bout : f_bout;
    const float* b1p   = g_b1p + flow * (LAYERS*WIDTH);
    const float* W1m   = g_W1m + flow * (LAYERS*WIDTH*DDIM);
    const float* Wom   = g_Wom + flow * (LAYERS*DDIM*PPD*WIDTH);

    for (int i = tid; i < TB*DDIM; i += NTHREADS) {
        int r = i >> 6, d = i & 63;
        sm[OFF_X0 + r*XPAD + d] = xin[row0*DDIM + i];
    }

    const float C1 = 8.0f / 1.01f;
    const float CADJ = 0.00125f;

    float ldacc[2] = {0.f, 0.f};
    int cur = OFF_X0, nxt = OFF_X1;

    __syncthreads();

    for (int layer = 0; layer < LAYERS; layer++) {
        // ---- W1 stage: 128 rows x 64 cols, split into 2 x 32-col buffers
        const float* W1l = W1m + layer*WIDTH*DDIM;
#pragma unroll
        for (int it = 0; it < 4; it++) {
            int i = tid + it*NTHREADS;              // 2048 float4s
            int rr = i >> 4, c4 = i & 15;
            float4 v = *(const float4*)&W1l[rr*DDIM + c4*4];
            *(float4*)&sm[OFF_WS + (c4 >> 3)*BUFSZ + rr*WQPAD + (c4 & 7)*4] = v;
        }
        __syncthreads();

        // ---- GEMM1 (balanced): warp w -> quads {w, 31-w}; rows {lane,lane+32}
        {
            const int qa = warpi, qb = 31 - warpi;
            const int ka  = (qa + 2) >> 1;          // <= 8, all in buf0
            const int kb4 = (qb + 2) >> 1;          // 9..16, spans both bufs

            unsigned long long acc[2][8];           // [row][0-3 quadA, 4-7 quadB]
#pragma unroll
            for (int ri = 0; ri < 2; ri++)
#pragma unroll
                for (int p = 0; p < 8; p++) acc[ri][p] = 0ull;

            const float* wa  = &sm[OFF_WS + (4*qa)*WQPAD];          // buf0
            const float* wb0 = &sm[OFF_WS + (4*qb)*WQPAD];          // buf0
            const float* wb1 = &sm[OFF_WS + BUFSZ + (4*qb)*WQPAD];  // buf1

#pragma unroll 2
            for (int kk = 0; kk < ka; kk++) {
                ulonglong2 x0 = *(const ulonglong2*)&sm[cur + (lane     )*XPAD + kk*4];
                ulonglong2 x1 = *(const ulonglong2*)&sm[cur + (lane + 32)*XPAD + kk*4];
#pragma unroll
                for (int p = 0; p < 4; p++) {
                    ulonglong2 wv = *(const ulonglong2*)&wa[p*WQPAD + kk*4];
                    acc[0][p] = ffma2(x0.x, wv.x, acc[0][p]);
                    acc[0][p] = ffma2(x0.y, wv.y, acc[0][p]);
                    acc[1][p] = ffma2(x1.x, wv.x, acc[1][p]);
                    acc[1][p] = ffma2(x1.y, wv.y, acc[1][p]);
                }
            }
#pragma unroll 2
            for (int kk = 0; kk < 8; kk++) {
                ulonglong2 x0 = *(const ulonglong2*)&sm[cur + (lane     )*XPAD + kk*4];
                ulonglong2 x1 = *(const ulonglong2*)&sm[cur + (lane + 32)*XPAD + kk*4];
#pragma unroll
                for (int p = 0; p < 4; p++) {
                    ulonglong2 wv = *(const ulonglong2*)&wb0[p*WQPAD + kk*4];
                    acc[0][4+p] = ffma2(x0.x, wv.x, acc[0][4+p]);
                    acc[0][4+p] = ffma2(x0.y, wv.y, acc[0][4+p]);
                    acc[1][4+p] = ffma2(x1.x, wv.x, acc[1][4+p]);
                    acc[1][4+p] = ffma2(x1.y, wv.y, acc[1][4+p]);
                }
            }
#pragma unroll 2
            for (int kk = 8; kk < kb4; kk++) {
                int kl = kk - 8;
                ulonglong2 x0 = *(const ulonglong2*)&sm[cur + (lane     )*XPAD + kk*4];
                ulonglong2 x1 = *(const ulonglong2*)&sm[cur + (lane + 32)*XPAD + kk*4];
#pragma unroll
                for (int p = 0; p < 4; p++) {
                    ulonglong2 wv = *(const ulonglong2*)&wb1[p*WQPAD + kl*4];
                    acc[0][4+p] = ffma2(x0.x, wv.x, acc[0][4+p]);
                    acc[0][4+p] = ffma2(x0.y, wv.y, acc[0][4+p]);
                    acc[1][4+p] = ffma2(x1.x, wv.x, acc[1][4+p]);
                    acc[1][4+p] = ffma2(x1.y, wv.y, acc[1][4+p]);
                }
            }

            float4 ba = *(const float4*)&b1p[layer*WIDTH + 4*qa];
            float4 bb = *(const float4*)&b1p[layer*WIDTH + 4*qb];
            float bav[4] = {ba.x, ba.y, ba.z, ba.w};
            float bbv[4] = {bb.x, bb.y, bb.z, bb.w};
#pragma unroll
            for (int ri = 0; ri < 2; ri++) {
                int r = lane + 32*ri;
                float ha[4], hb[4];
#pragma unroll
                for (int p = 0; p < 4; p++) {
                    float2 ua = unpack2(acc[ri][p]);
                    ha[p] = fmaxf(ua.x + ua.y + bav[p], 0.f);
                    float2 ub = unpack2(acc[ri][4+p]);
                    hb[p] = fmaxf(ub.x + ub.y + bbv[p], 0.f);
                }
                *(float4*)&sm[OFF_H + r*HPAD + 4*qa] = make_float4(ha[0],ha[1],ha[2],ha[3]);
                *(float4*)&sm[OFF_H + r*HPAD + 4*qb] = make_float4(hb[0],hb[1],hb[2],hb[3]);
            }
        }
        __syncthreads();   // H ready

        // ---- GEMM2 + streamed spline over 4 chunks of 16 dims ----
        for (int chunk = 0; chunk < NCHUNK; chunk++) {
            const int d0 = chunk * DG;
            const int d  = d0 + dl;
            const int kmax = kmax_of(d);                // warp-uniform
            const int nq   = kmax_of(d0 + 15) >> 5;     // CTA-uniform (1..4)
            const float* Wol = Wom + layer*DDIM*PPD*WIDTH;
            const float* bo  = boutg + (layer*DDIM + d)*PPD;

            float pr[2][8];
            float st_xi[2], st_invdx[2], st_yk[2], st_dyv[2], st_sk[2];
            int   st_k[2];

            // ===== phase 1: widths -> bin index, xi, invdx =====
            gemm2_pass<0, 8>(sm, Wol, bo, d0, dl, lane, nq, kmax, pr);
#pragma unroll
            for (int ri = 0; ri < 2; ri++) {
                float mw = pr[ri][0];
#pragma unroll
                for (int j = 1; j < 8; j++) mw = fmaxf(mw, pr[ri][j]);
                float ew[8]; float swv = 0.f;
#pragma unroll
                for (int j = 0; j < 8; j++) { ew[j] = __expf(pr[ri][j] - mw); swv += ew[j]; }
                float isc = __frcp_rn(swv) * C1;
                float cadj = CADJ * C1;

                float xraw = sm[cur + (lane + 32*ri)*XPAD + d];
                float xc = fminf(fmaxf(xraw, -BI), BI);

                float xl = -BI;
                float xk = -BI, xk1 = -BI;
                int k = 0;
#pragma unroll
                for (int j = 0; j < 8; j++) {
                    float wj = ew[j]*isc + cadj;
                    float xr2 = xl + wj;
                    if (xc >= xl) { k = j; xk = xl; xk1 = xr2; }
                    xl = xr2;
                }
                float invdx = __frcp_rn(xk1 - xk);
                st_invdx[ri] = invdx;
                st_xi[ri] = (xc - xk) * invdx;
                st_k[ri] = k;
            }

            // ===== phase 2: heights -> yk, dyv, sk =====
            gemm2_pass<8, 8>(sm, Wol, bo, d0, dl, lane, nq, kmax, pr);
#pragma unroll
            for (int ri = 0; ri < 2; ri++) {
                float mh = pr[ri][0];
#pragma unroll
                for (int j = 1; j < 8; j++) mh = fmaxf(mh, pr[ri][j]);
                float eh[8]; float shv = 0.f;
#pragma unroll
                for (int j = 0; j < 8; j++) { eh[j] = __expf(pr[ri][j] - mh); shv += eh[j]; }
                float isc = __frcp_rn(shv) * C1;
                float cadj = CADJ * C1;

                const int k = st_k[ri];
                float yl = -BI;
                float yk = -BI, yk1 = -BI;
#pragma unroll
                for (int j = 0; j < 8; j++) {
                    float hj = eh[j]*isc + cadj;
                    float yr2 = yl + hj;
                    if (j == k) { yk = yl; yk1 = yr2; }
                    yl = yr2;
                }
                st_yk[ri] = yk;
                st_dyv[ri] = yk1 - yk;
                st_sk[ri] = st_dyv[ri] * st_invdx[ri];
            }

            // ===== phase 3: selective derivative dots -> finish =====
            float dotA[2], dotB[2];
            gemm2_pass3(sm, Wol, d0, dl, lane, nq, kmax, st_k, dotA, dotB);
#pragma unroll
            for (int ri = 0; ri < 2; ri++) {
                const int k = st_k[ri];
                float dk  = 1.f, dk1 = 1.f;
                if (k >= 1) dk  = softplus_fast(dotA[ri] + bo[16 + k - 1]) + 0.001f;
                if (k <= 6) dk1 = softplus_fast(dotB[ri] + bo[16 + k]) + 0.001f;

                float xi = st_xi[ri];
                float omx = 1.f - xi;
                float xiomx = xi * omx;
                float sk = st_sk[ri];
                float den = sk + (dk1 + dk - 2.f*sk) * xiomx;
                float invden = __frcp_rn(den);
                float nume = sk*xi*xi + dk*xiomx;
                float outv = st_yk[ri] + st_dyv[ri] * nume * invden;
                float ldn = dk1*xi*xi + 2.f*sk*xiomx + dk*omx*omx;
                float ld = __logf(sk*sk*ldn*(invden*invden));

                float xraw = sm[cur + (lane + 32*ri)*XPAD + d];
                bool inside = (xraw > -BI) && (xraw < BI);
                float xo2 = inside ? outv : xraw;
                sm[nxt + (lane + 32*ri)*XPAD + (DDIM-1 - d)] = xo2;  // reversal fused
                ldacc[ri] += inside ? ld : 0.f;
            }
        }

        __syncthreads();   // X(nxt) ready
        int t = cur; cur = nxt; nxt = t;
    }

    // ---- outputs: [xo (B*64) | ldf (B) | yo (B*64) | ldg (B)]
    const int xbase  = flow ? (BATCH*DDIM + BATCH) : 0;
    const int ldbase = flow ? (2*BATCH*DDIM + BATCH) : (BATCH*DDIM);

    for (int i = tid; i < TB*DDIM; i += NTHREADS) {
        int rr = i >> 6, dd = i & 63;
        out[xbase + row0*DDIM + i] = sm[cur + rr*XPAD + dd];
    }

    // log-det reduction: 16 dim-class partials per row
    float* red = &sm[OFF_WS];
#pragma unroll
    for (int ri = 0; ri < 2; ri++)
        red[(lane + 32*ri)*16 + dl] = ldacc[ri];
    __syncthreads();
    if (tid < TB) {
        float s = 0.f;
#pragma unroll
        for (int j = 0; j < 16; j++) s += red[tid*16 + j];
        out[ldbase + row0 + tid] = s;
    }
}

// ---------------------------------------------------------------------------
extern "C" void kernel_launch(void* const* d_in, const int* in_sizes, int n_in,
                              void* d_out, int out_size)
{
    const float* x      = (const float*)d_in[0];
    const float* y      = (const float*)d_in[1];
    const float* f_W1   = (const float*)d_in[2];
    const float* f_b1   = (const float*)d_in[3];
    const float* f_Wout = (const float*)d_in[4];
    const float* f_bout = (const float*)d_in[5];
    const float* g_W1   = (const float*)d_in[6];
    const float* g_b1   = (const float*)d_in[7];
    const float* g_Wout = (const float*)d_in[8];
    const float* g_bout = (const float*)d_in[9];
    float* out = (float*)d_out;

    cudaFuncSetAttribute(maf_kernel, cudaFuncAttributeMaxDynamicSharedMemorySize, SMEM_BYTES);

    prep_kernel<<<1024, 256>>>(f_W1, f_Wout, g_W1, g_Wout, f_b1, g_b1);

    dim3 grid(BATCH/TB, 2);
    maf_kernel<<<grid, NTHREADS, SMEM_BYTES>>>(x, y, f_bout, g_bout, out);
}

// round 17
// speedup vs baseline: 1.4216x; 1.0186x over previous
#include <cuda_runtime.h>

#define LAYERS   8
#define WIDTH    128
#define DDIM     64
#define KNOTS    8
#define PPD      23          // 3*KNOTS-1
#define BATCH    16384
#define TB       64          // batch rows per CTA
#define NTHREADS 512
#define DG       16          // dims per chunk (1 per warp)
#define NCHUNK   (DDIM/DG)   // 4
#define XPAD     68
#define HPAD     132
#define WQPAD    36          // 32-col quarter staging row stride
#define BUFSZ    (128*WQPAD) // one ping-pong buffer (128 rows)
#define BI       4.0f

// shared memory layout (float offsets)
#define OFF_X0   0
#define OFF_X1   (TB*XPAD)                    // 4352
#define OFF_H    (2*TB*XPAD)                  // 8704
#define OFF_WS   (2*TB*XPAD + TB*HPAD)        // 17152
#define SMEM_FLOATS (OFF_WS + 2*BUFSZ)        // 17152 + 9216 = 26368
#define SMEM_BYTES  (SMEM_FLOATS*4)           // 105472 B -> 2 CTAs/SM

// Pre-masked, degree-sorted weights (static device scratch).
// g_Wom padded +128: pass-3 staging reads one row past the logical end.
__device__ float g_W1m[2*LAYERS*WIDTH*DDIM];
__device__ float g_Wom[2*LAYERS*DDIM*PPD*WIDTH + 128];
__device__ float g_b1p[2*LAYERS*WIDTH];

// ---------------------------------------------------------------------------
// packed fp32x2 FMA: 2 MACs per fma-pipe issue slot
// ---------------------------------------------------------------------------
__device__ __forceinline__ unsigned long long ffma2(unsigned long long a,
                                                    unsigned long long b,
                                                    unsigned long long c)
{
    unsigned long long d;
    asm("fma.rn.f32x2 %0, %1, %2, %3;" : "=l"(d) : "l"(a), "l"(b), "l"(c));
    return d;
}
__device__ __forceinline__ float2 unpack2(unsigned long long v)
{
    float2 r;
    asm("mov.b64 {%0, %1}, %2;" : "=f"(r.x), "=f"(r.y) : "l"(v));
    return r;
}

// cp.async 16B: global -> shared without register round-trip (LDGSTS)
__device__ __forceinline__ void cp16(void* smem_dst, const void* gmem_src)
{
    unsigned int s = (unsigned int)__cvta_generic_to_shared(smem_dst);
    asm volatile("cp.async.cg.shared.global [%0], [%1], 16;"
                 :: "r"(s), "l"(gmem_src) : "memory");
}
__device__ __forceinline__ void cp_commit() { asm volatile("cp.async.commit_group;" ::: "memory"); }
__device__ __forceinline__ void cp_waitall() { asm volatile("cp.async.wait_group 0;" ::: "memory"); }

// softplus = max(v,0) + log(1 + exp(-|v|))   (2 MUFU, no library tail)
__device__ __forceinline__ float softplus_fast(float v)
{
    float t = __expf(-fabsf(v));
    return fmaxf(v, 0.f) + __logf(1.f + t);
}

// ---------------------------------------------------------------------------
// Degree-sorted hidden permutation.
// ---------------------------------------------------------------------------
__host__ __device__ __forceinline__ int sdeg(int j) { return (j < 6) ? (j/3) : ((j-2)>>1); }
__host__ __device__ __forceinline__ int permf(int j)
{
    if (j < 3)  return (j == 0) ? 0 : (j == 1 ? 63 : 126);
    if (j < 6)  return (j == 3) ? 1 : (j == 4 ? 64 : 127);
    int v = (j - 2) >> 1;
    return ((j & 1) == 0) ? v : v + 63;
}
// prefix length of dim d over sorted hidden, rounded up to 8
__device__ __forceinline__ int kmax_of(int d)
{
    int n = (d == 0) ? 0 : (d == 1 ? 3 : 2*d + 2);
    n = (n + 7) & ~7;
    return n > 128 ? 128 : n;
}

// ---------------------------------------------------------------------------
// Prep: mask + permute weights once per launch.
// ---------------------------------------------------------------------------
__global__ void prep_kernel(const float* __restrict__ fW1, const float* __restrict__ fWo,
                            const float* __restrict__ gW1, const float* __restrict__ gWo,
                            const float* __restrict__ fb1, const float* __restrict__ gb1)
{
    const int N1 = LAYERS*WIDTH*DDIM;
    const int N2 = LAYERS*DDIM*PPD*WIDTH;
    const int stride = gridDim.x * blockDim.x;
    const int t0 = blockIdx.x*blockDim.x + threadIdx.x;

    for (int i = t0; i < 2*N1; i += stride) {
        int fl = i / N1, j = i - fl*N1;
        int row = (j >> 6) & (WIDTH-1);
        int c = j & (DDIM-1);
        int l = j >> 13;
        const float* s = fl ? gW1 : fW1;
        int src = permf(row);
        g_W1m[i] = (c <= sdeg(row)) ? s[l*WIDTH*DDIM + src*DDIM + c] : 0.f;
    }
    for (int i = t0; i < 2*N2; i += stride) {
        int fl = i / N2, j = i - fl*N2;
        int col = j & (WIDTH-1);
        int o = (j >> 7) % (DDIM*PPD);
        int l = j / (DDIM*PPD*WIDTH);
        int d = o / PPD;
        const float* s = fl ? gWo : fWo;
        int src = permf(col);
        g_Wom[i] = (sdeg(col) < d) ? s[l*(DDIM*PPD)*WIDTH + o*WIDTH + src] : 0.f;
    }
    if (t0 < 128) g_Wom[2*N2 + t0] = 0.f;   // pad tail
    for (int i = t0; i < 2*LAYERS*WIDTH; i += stride) {
        int fl = i / (LAYERS*WIDTH), j = i - fl*(LAYERS*WIDTH);
        int l = j >> 7, w = j & (WIDTH-1);
        const float* s = fl ? gb1 : fb1;
        g_b1p[i] = s[l*WIDTH + permf(w)];
    }
}

// ---------------------------------------------------------------------------
// GEMM2 quarter stage (async issue only): 16 dims x 8 params x 32 cols of
// Wout -> buffer (q&1).  Predicated per dim on kmax.  Caller pairs with
// cp_waitall() before the consuming barrier.
// ---------------------------------------------------------------------------
__device__ __forceinline__ void stage_q_async(
    float* sm, const float* __restrict__ Wol, int d0, int pbase, int q)
{
    float* buf = &sm[OFF_WS + (q & 1)*BUFSZ];
#pragma unroll
    for (int it = 0; it < 2; it++) {
        int i = threadIdx.x + it*NTHREADS;      // 1024 float4s
        int rr = i >> 3, c4 = i & 7;
        int dd = rr >> 3, pp = rr & 7;
        if (kmax_of(d0 + dd) > 32*q)
            cp16(&buf[rr*WQPAD + c4*4],
                 &Wol[((d0+dd)*PPD + pbase + pp)*WIDTH + q*32 + c4*4]);
    }
    cp_commit();
}

// ---------------------------------------------------------------------------
// GEMM2 pass (phases 1/2): PCNT params x 2 rows over this warp's dim
// K-prefix.  cp.async-pipelined quarter staging: issue q+1, compute q,
// wait, barrier.
// ---------------------------------------------------------------------------
template<int PBASE, int PCNT>
__device__ __forceinline__ void gemm2_pass(
    float* sm, const float* __restrict__ Wol, const float* __restrict__ bo,
    int d0, int dl, int lane, int nq, int kmax, float out[2][8])
{
    unsigned long long acc[2][PCNT];
#pragma unroll
    for (int ri = 0; ri < 2; ri++)
#pragma unroll
        for (int p = 0; p < PCNT; p++) acc[ri][p] = 0ull;

    stage_q_async(sm, Wol, d0, PBASE, 0);
    cp_waitall();
    __syncthreads();

    for (int q = 0; q < nq; q++) {
        if (q + 1 < nq) stage_q_async(sm, Wol, d0, PBASE, q + 1);  // prefetch

        int bound = kmax - 32*q;                    // warp-uniform
        bound = bound < 0 ? 0 : (bound > 32 ? 32 : bound);
        const float* hbase = &sm[OFF_H + q*32];
        const float* wsp   = &sm[OFF_WS + (q & 1)*BUFSZ + (dl*8)*WQPAD];
#pragma unroll 4
        for (int k4 = 0; k4 < (bound >> 2); k4++) {
            ulonglong2 h0 = *(const ulonglong2*)&hbase[(lane     )*HPAD + k4*4];
            ulonglong2 h1 = *(const ulonglong2*)&hbase[(lane + 32)*HPAD + k4*4];
#pragma unroll
            for (int p = 0; p < PCNT; p++) {
                ulonglong2 wv = *(const ulonglong2*)&wsp[p*WQPAD + k4*4];
                acc[0][p] = ffma2(h0.x, wv.x, acc[0][p]);
                acc[0][p] = ffma2(h0.y, wv.y, acc[0][p]);
                acc[1][p] = ffma2(h1.x, wv.x, acc[1][p]);
                acc[1][p] = ffma2(h1.y, wv.y, acc[1][p]);
            }
        }
        cp_waitall();
        __syncthreads();
    }

#pragma unroll
    for (int ri = 0; ri < 2; ri++)
#pragma unroll
        for (int p = 0; p < PCNT; p++) {
            float2 u = unpack2(acc[ri][p]);
            out[ri][p] = u.x + u.y + bo[PBASE + p];
        }
}

// ---------------------------------------------------------------------------
// GEMM2 phase 3 (selective, async-pipelined): only the 2 derivative params
// actually used (rows k-1 and k) are accumulated.
// ---------------------------------------------------------------------------
__device__ __forceinline__ void gemm2_pass3(
    float* sm, const float* __restrict__ Wol,
    int d0, int dl, int lane, int nq, int kmax,
    const int st_k[2], float dotA[2], float dotB[2])
{
    unsigned long long accA[2] = {0ull, 0ull};
    unsigned long long accB[2] = {0ull, 0ull};
    const int rA0 = dl*8 + max(st_k[0] - 1, 0);
    const int rB0 = dl*8 + min(st_k[0], 6);
    const int rA1 = dl*8 + max(st_k[1] - 1, 0);
    const int rB1 = dl*8 + min(st_k[1], 6);

    stage_q_async(sm, Wol, d0, 16, 0);
    cp_waitall();
    __syncthreads();

    for (int q = 0; q < nq; q++) {
        if (q + 1 < nq) stage_q_async(sm, Wol, d0, 16, q + 1);    // prefetch

        int bound = kmax - 32*q;                    // warp-uniform
        bound = bound < 0 ? 0 : (bound > 32 ? 32 : bound);
        const float* hbase = &sm[OFF_H + q*32];
        const float* bufq  = &sm[OFF_WS + (q & 1)*BUFSZ];
#pragma unroll 4
        for (int k4 = 0; k4 < (bound >> 2); k4++) {
            ulonglong2 h0 = *(const ulonglong2*)&hbase[(lane     )*HPAD + k4*4];
            ulonglong2 h1 = *(const ulonglong2*)&hbase[(lane + 32)*HPAD + k4*4];
            ulonglong2 wA0 = *(const ulonglong2*)&bufq[rA0*WQPAD + k4*4];
            ulonglong2 wB0 = *(const ulonglong2*)&bufq[rB0*WQPAD + k4*4];
            ulonglong2 wA1 = *(const ulonglong2*)&bufq[rA1*WQPAD + k4*4];
            ulonglong2 wB1 = *(const ulonglong2*)&bufq[rB1*WQPAD + k4*4];
            accA[0] = ffma2(h0.x, wA0.x, accA[0]);
            accA[0] = ffma2(h0.y, wA0.y, accA[0]);
            accB[0] = ffma2(h0.x, wB0.x, accB[0]);
            accB[0] = ffma2(h0.y, wB0.y, accB[0]);
            accA[1] = ffma2(h1.x, wA1.x, accA[1]);
            accA[1] = ffma2(h1.y, wA1.y, accA[1]);
            accB[1] = ffma2(h1.x, wB1.x, accB[1]);
            accB[1] = ffma2(h1.y, wB1.y, accB[1]);
        }
        cp_waitall();
        __syncthreads();
    }

#pragma unroll
    for (int ri = 0; ri < 2; ri++) {
        float2 ua = unpack2(ri == 0 ? accA[0] : accA[1]);
        float2 ub = unpack2(ri == 0 ? accB[0] : accB[1]);
        dotA[ri] = ua.x + ua.y;
        dotB[ri] = ub.x + ub.y;
    }
}

// ---------------------------------------------------------------------------
// Main kernel: one CTA (512 thr) = 64 rows through all 8 layers; 2 CTAs/SM.
// Warp w owns dim d0+w (GEMM2) / hidden quads {w, 31-w} (GEMM1); lane owns
// rows {lane, lane+32}.  Spline streamed in 3 phases; cp.async staging.
// ---------------------------------------------------------------------------
__global__ __launch_bounds__(NTHREADS, 2)
void maf_kernel(const float* __restrict__ xin_f, const float* __restrict__ xin_g,
                const float* __restrict__ f_bout, const float* __restrict__ g_bout,
                float* __restrict__ out)
{
    extern __shared__ float sm[];
    const int tid   = threadIdx.x;
    const int flow  = blockIdx.y;
    const int row0  = blockIdx.x * TB;
    const int warpi = tid >> 5;    // 0..15
    const int lane  = tid & 31;
    const int dl    = warpi;       // dim lane within chunk

    const float* xin   = flow ? xin_g  : xin_f;
    const float* boutg = flow ? g_bout : f_bout;
    const float* b1p   = g_b1p + flow * (LAYERS*WIDTH);
    const float* W1m   = g_W1m + flow * (LAYERS*WIDTH*DDIM);
    const float* Wom   = g_Wom + flow * (LAYERS*DDIM*PPD*WIDTH);

    for (int i = tid; i < TB*DDIM; i += NTHREADS) {
        int r = i >> 6, d = i & 63;
        sm[OFF_X0 + r*XPAD + d] = xin[row0*DDIM + i];
    }

    const float C1 = 8.0f / 1.01f;
    const float CADJ = 0.00125f;

    float ldacc[2] = {0.f, 0.f};
    int cur = OFF_X0, nxt = OFF_X1;

    __syncthreads();

    for (int layer = 0; layer < LAYERS; layer++) {
        // ---- W1 stage (cp.async): 128 rows x 64 cols -> 2 x 32-col buffers
        const float* W1l = W1m + layer*WIDTH*DDIM;
#pragma unroll
        for (int it = 0; it < 4; it++) {
            int i = tid + it*NTHREADS;              // 2048 float4s
            int rr = i >> 4, c4 = i & 15;
            cp16(&sm[OFF_WS + (c4 >> 3)*BUFSZ + rr*WQPAD + (c4 & 7)*4],
                 &W1l[rr*DDIM + c4*4]);
        }
        cp_commit();
        cp_waitall();
        __syncthreads();

        // ---- GEMM1 (balanced): warp w -> quads {w, 31-w}; rows {lane,lane+32}
        {
            const int qa = warpi, qb = 31 - warpi;
            const int ka  = (qa + 2) >> 1;          // <= 8, all in buf0
            const int kb4 = (qb + 2) >> 1;          // 9..16, spans both bufs

            unsigned long long acc[2][8];           // [row][0-3 quadA, 4-7 quadB]
#pragma unroll
            for (int ri = 0; ri < 2; ri++)
#pragma unroll
                for (int p = 0; p < 8; p++) acc[ri][p] = 0ull;

            const float* wa  = &sm[OFF_WS + (4*qa)*WQPAD];          // buf0
            const float* wb0 = &sm[OFF_WS + (4*qb)*WQPAD];          // buf0
            const float* wb1 = &sm[OFF_WS + BUFSZ + (4*qb)*WQPAD];  // buf1

#pragma unroll 2
            for (int kk = 0; kk < ka; kk++) {
                ulonglong2 x0 = *(const ulonglong2*)&sm[cur + (lane     )*XPAD + kk*4];
                ulonglong2 x1 = *(const ulonglong2*)&sm[cur + (lane + 32)*XPAD + kk*4];
#pragma unroll
                for (int p = 0; p < 4; p++) {
                    ulonglong2 wv = *(const ulonglong2*)&wa[p*WQPAD + kk*4];
                    acc[0][p] = ffma2(x0.x, wv.x, acc[0][p]);
                    acc[0][p] = ffma2(x0.y, wv.y, acc[0][p]);
                    acc[1][p] = ffma2(x1.x, wv.x, acc[1][p]);
                    acc[1][p] = ffma2(x1.y, wv.y, acc[1][p]);
                }
            }
#pragma unroll 2
            for (int kk = 0; kk < 8; kk++) {
                ulonglong2 x0 = *(const ulonglong2*)&sm[cur + (lane     )*XPAD + kk*4];
                ulonglong2 x1 = *(const ulonglong2*)&sm[cur + (lane + 32)*XPAD + kk*4];
#pragma unroll
                for (int p = 0; p < 4; p++) {
                    ulonglong2 wv = *(const ulonglong2*)&wb0[p*WQPAD + kk*4];
                    acc[0][4+p] = ffma2(x0.x, wv.x, acc[0][4+p]);
                    acc[0][4+p] = ffma2(x0.y, wv.y, acc[0][4+p]);
                    acc[1][4+p] = ffma2(x1.x, wv.x, acc[1][4+p]);
                    acc[1][4+p] = ffma2(x1.y, wv.y, acc[1][4+p]);
                }
            }
#pragma unroll 2
            for (int kk = 8; kk < kb4; kk++) {
                int kl = kk - 8;
                ulonglong2 x0 = *(const ulonglong2*)&sm[cur + (lane     )*XPAD + kk*4];
                ulonglong2 x1 = *(const ulonglong2*)&sm[cur + (lane + 32)*XPAD + kk*4];
#pragma unroll
                for (int p = 0; p < 4; p++) {
                    ulonglong2 wv = *(const ulonglong2*)&wb1[p*WQPAD + kl*4];
                    acc[0][4+p] = ffma2(x0.x, wv.x, acc[0][4+p]);
                    acc[0][4+p] = ffma2(x0.y, wv.y, acc[0][4+p]);
                    acc[1][4+p] = ffma2(x1.x, wv.x, acc[1][4+p]);
                    acc[1][4+p] = ffma2(x1.y, wv.y, acc[1][4+p]);
                }
            }

            float4 ba = *(const float4*)&b1p[layer*WIDTH + 4*qa];
            float4 bb = *(const float4*)&b1p[layer*WIDTH + 4*qb];
            float bav[4] = {ba.x, ba.y, ba.z, ba.w};
            float bbv[4] = {bb.x, bb.y, bb.z, bb.w};
#pragma unroll
            for (int ri = 0; ri < 2; ri++) {
                int r = lane + 32*ri;
                float ha[4], hb[4];
#pragma unroll
                for (int p = 0; p < 4; p++) {
                    float2 ua = unpack2(acc[ri][p]);
                    ha[p] = fmaxf(ua.x + ua.y + bav[p], 0.f);
                    float2 ub = unpack2(acc[ri][4+p]);
                    hb[p] = fmaxf(ub.x + ub.y + bbv[p], 0.f);
                }
                *(float4*)&sm[OFF_H + r*HPAD + 4*qa] = make_float4(ha[0],ha[1],ha[2],ha[3]);
                *(float4*)&sm[OFF_H + r*HPAD + 4*qb] = make_float4(hb[0],hb[1],hb[2],hb[3]);
            }
        }
        __syncthreads();   // H ready

        // ---- GEMM2 + streamed spline over 4 chunks of 16 dims ----
        for (int chunk = 0; chunk < NCHUNK; chunk++) {
            const int d0 = chunk * DG;
            const int d  = d0 + dl;
            const int kmax = kmax_of(d);                // warp-uniform
            const int nq   = kmax_of(d0 + 15) >> 5;     // CTA-uniform (1..4)
            const float* Wol = Wom + layer*DDIM*PPD*WIDTH;
            const float* bo  = boutg + (layer*DDIM + d)*PPD;

            float pr[2][8];
            float st_xi[2], st_invdx[2], st_yk[2], st_dyv[2], st_sk[2];
            int   st_k[2];

            // ===== phase 1: widths -> bin index, xi, invdx =====
            gemm2_pass<0, 8>(sm, Wol, bo, d0, dl, lane, nq, kmax, pr);
#pragma unroll
            for (int ri = 0; ri < 2; ri++) {
                float mw = pr[ri][0];
#pragma unroll
                for (int j = 1; j < 8; j++) mw = fmaxf(mw, pr[ri][j]);
                float ew[8]; float swv = 0.f;
#pragma unroll
                for (int j = 0; j < 8; j++) { ew[j] = __expf(pr[ri][j] - mw); swv += ew[j]; }
                float isc = __frcp_rn(swv) * C1;
                float cadj = CADJ * C1;

                float xraw = sm[cur + (lane + 32*ri)*XPAD + d];
                float xc = fminf(fmaxf(xraw, -BI), BI);

                float xl = -BI;
                float xk = -BI, xk1 = -BI;
                int k = 0;
#pragma unroll
                for (int j = 0; j < 8; j++) {
                    float wj = ew[j]*isc + cadj;
                    float xr2 = xl + wj;
                    if (xc >= xl) { k = j; xk = xl; xk1 = xr2; }
                    xl = xr2;
                }
                float invdx = __frcp_rn(xk1 - xk);
                st_invdx[ri] = invdx;
                st_xi[ri] = (xc - xk) * invdx;
                st_k[ri] = k;
            }

            // ===== phase 2: heights -> yk, dyv, sk =====
            gemm2_pass<8, 8>(sm, Wol, bo, d0, dl, lane, nq, kmax, pr);
#pragma unroll
            for (int ri = 0; ri < 2; ri++) {
                float mh = pr[ri][0];
#pragma unroll
                for (int j = 1; j < 8; j++) mh = fmaxf(mh, pr[ri][j]);
                float eh[8]; float shv = 0.f;
#pragma unroll
                for (int j = 0; j < 8; j++) { eh[j] = __expf(pr[ri][j] - mh); shv += eh[j]; }
                float isc = __frcp_rn(shv) * C1;
                float cadj = CADJ * C1;

                const int k = st_k[ri];
                float yl = -BI;
                float yk = -BI, yk1 = -BI;
#pragma unroll
                for (int j = 0; j < 8; j++) {
                    float hj = eh[j]*isc + cadj;
                    float yr2 = yl + hj;
                    if (j == k) { yk = yl; yk1 = yr2; }
                    yl = yr2;
                }
                st_yk[ri] = yk;
                st_dyv[ri] = yk1 - yk;
                st_sk[ri] = st_dyv[ri] * st_invdx[ri];
            }

            // ===== phase 3: selective derivative dots -> finish =====
            float dotA[2], dotB[2];
            gemm2_pass3(sm, Wol, d0, dl, lane, nq, kmax, st_k, dotA, dotB);
#pragma unroll
            for (int ri = 0; ri < 2; ri++) {
                const int k = st_k[ri];
                float dk  = 1.f, dk1 = 1.f;
                if (k >= 1) dk  = softplus_fast(dotA[ri] + bo[16 + k - 1]) + 0.001f;
                if (k <= 6) dk1 = softplus_fast(dotB[ri] + bo[16 + k]) + 0.001f;

                float xi = st_xi[ri];
                float omx = 1.f - xi;
                float xiomx = xi * omx;
                float sk = st_sk[ri];
                float den = sk + (dk1 + dk - 2.f*sk) * xiomx;
                float invden = __frcp_rn(den);
                float nume = sk*xi*xi + dk*xiomx;
                float outv = st_yk[ri] + st_dyv[ri] * nume * invden;
                float ldn = dk1*xi*xi + 2.f*sk*xiomx + dk*omx*omx;
                float ld = __logf(sk*sk*ldn*(invden*invden));

                float xraw = sm[cur + (lane + 32*ri)*XPAD + d];
                bool inside = (xraw > -BI) && (xraw < BI);
                float xo2 = inside ? outv : xraw;
                sm[nxt + (lane + 32*ri)*XPAD + (DDIM-1 - d)] = xo2;  // reversal fused
                ldacc[ri] += inside ? ld : 0.f;
            }
        }

        __syncthreads();   // X(nxt) ready
        int t = cur; cur = nxt; nxt = t;
    }

    // ---- outputs: [xo (B*64) | ldf (B) | yo (B*64) | ldg (B)]
    const int xbase  = flow ? (BATCH*DDIM + BATCH) : 0;
    const int ldbase = flow ? (2*BATCH*DDIM + BATCH) : (BATCH*DDIM);

    for (int i = tid; i < TB*DDIM; i += NTHREADS) {
        int rr = i >> 6, dd = i & 63;
        out[xbase + row0*DDIM + i] = sm[cur + rr*XPAD + dd];
    }

    // log-det reduction: 16 dim-class partials per row
    float* red = &sm[OFF_WS];
#pragma unroll
    for (int ri = 0; ri < 2; ri++)
        red[(lane + 32*ri)*16 + dl] = ldacc[ri];
    __syncthreads();
    if (tid < TB) {
        float s = 0.f;
#pragma unroll
        for (int j = 0; j < 16; j++) s += red[tid*16 + j];
        out[ldbase + row0 + tid] = s;
    }
}

// ---------------------------------------------------------------------------
extern "C" void kernel_launch(void* const* d_in, const int* in_sizes, int n_in,
                              void* d_out, int out_size)
{
    const float* x      = (const float*)d_in[0];
    const float* y      = (const float*)d_in[1];
    const float* f_W1   = (const float*)d_in[2];
    const float* f_b1   = (const float*)d_in[3];
    const float* f_Wout = (const float*)d_in[4];
    const float* f_bout = (const float*)d_in[5];
    const float* g_W1   = (const float*)d_in[6];
    const float* g_b1   = (const float*)d_in[7];
    const float* g_Wout = (const float*)d_in[8];
    const float* g_bout = (const float*)d_in[9];
    float* out = (float*)d_out;

    cudaFuncSetAttribute(maf_kernel, cudaFuncAttributeMaxDynamicSharedMemorySize, SMEM_BYTES);

    prep_kernel<<<1024, 256>>>(f_W1, f_Wout, g_W1, g_Wout, f_b1, g_b1);

    dim3 grid(BATCH/TB, 2);
    maf_kernel<<<grid, NTHREADS, SMEM_BYTES>>>(x, y, f_bout, g_bout, out);
}